// round 1
// baseline (speedup 1.0000x reference)
#include <cuda_runtime.h>
#include <math.h>

#define MM      8
#define AA      48
#define NSPEC   4
#define NPAIRCH 10
#define NSHFR   16
#define NSHFA   4
#define NSHFZ   8
#define RADDIM  (NSPEC * NSHFR)            /* 64  */
#define ANGDIM  (NPAIRCH * NSHFA * NSHFZ)  /* 320 */
#define OUTDIM  (RADDIM + ANGDIM)          /* 384 */
#define RCR_F   5.2f
#define RCA_F   3.5f
#define PI_F    3.14159265358979323846f
#define NT      256
#define NWARPS  (NT / 32)

__global__ __launch_bounds__(NT, 1) void aev_kernel(
    const float* __restrict__ coords,   // (M, A, 3)
    const float* __restrict__ EtaR,     // (1,)
    const float* __restrict__ ShfR,     // (16,)
    const float* __restrict__ EtaA,     // (1,)
    const float* __restrict__ Zeta,     // (1,)
    const float* __restrict__ ShfA,     // (4,)
    const float* __restrict__ ShfZ,     // (8,)
    const int*   __restrict__ species,  // (M, A)
    const int*   __restrict__ triu,     // (4, 4)
    float*       __restrict__ out)      // (M, A, 384)
{
    __shared__ float px[AA], py[AA], pz[AA];
    __shared__ int   sp[AA];
    __shared__ float vx[AA], vy[AA], vz[AA], dd[AA];
    __shared__ unsigned char pv[AA];
    __shared__ int   nbr[AA];
    __shared__ int   nnbr;
    __shared__ float rad[RADDIM];
    __shared__ float ang[ANGDIM];
    __shared__ float s_shfr[NSHFR], s_shfa[NSHFA];
    __shared__ float s_cz[NSHFZ], s_sz[NSHFZ];
    __shared__ int   s_triu[NSPEC * NSPEC];
    __shared__ float s_etaR, s_etaA, s_zeta;

    const int mi  = blockIdx.x;           // 0 .. M*A-1
    const int m   = mi / AA;
    const int i   = mi % AA;
    const int tid = threadIdx.x;

    if (tid == 0) { nnbr = 0; s_etaR = EtaR[0]; s_etaA = EtaA[0]; s_zeta = Zeta[0]; }
    if (tid < NSHFR) s_shfr[tid] = ShfR[tid];
    if (tid < NSHFA) s_shfa[tid] = ShfA[tid];
    if (tid < NSHFZ) { float z = ShfZ[tid]; s_cz[tid] = cosf(z); s_sz[tid] = sinf(z); }
    if (tid < NSPEC * NSPEC) s_triu[tid] = triu[tid];
    if (tid < AA) {
        px[tid] = coords[(m * AA + tid) * 3 + 0];
        py[tid] = coords[(m * AA + tid) * 3 + 1];
        pz[tid] = coords[(m * AA + tid) * 3 + 2];
        sp[tid] = species[m * AA + tid];
    }
    if (tid < RADDIM) rad[tid] = 0.0f;
    #pragma unroll
    for (int t = tid; t < ANGDIM; t += NT) ang[t] = 0.0f;
    __syncthreads();

    const float xi  = px[i], yi = py[i], zi = pz[i];
    const int   spi = sp[i];

    // ---- distances + neighbor list (one thread per j) ----
    if (tid < AA) {
        float dx = px[tid] - xi;          // v[m,i,j] = c[j] - c[i]
        float dy = py[tid] - yi;
        float dz = pz[tid] - zi;
        float d2 = dx * dx + dy * dy + dz * dz;
        float d  = sqrtf(d2 > 0.0f ? d2 : 1.0f);
        vx[tid] = dx; vy[tid] = dy; vz[tid] = dz; dd[tid] = d;
        bool pvb = (spi >= 0) && (sp[tid] >= 0) && (tid != i);
        pv[tid] = (unsigned char)pvb;
        if (pvb && d <= RCA_F) {
            int idx = atomicAdd(&nnbr, 1);
            nbr[idx] = tid;
        }
    }
    __syncthreads();

    // ---- radial AEV: (j, r) work items, SMEM-atomic accumulation ----
    {
        const float etaR = s_etaR;
        for (int t = tid; t < AA * NSHFR; t += NT) {
            int j = t >> 4;
            int r = t & 15;
            float d = dd[j];
            if (pv[j] && d <= RCR_F) {
                float fc   = 0.5f * cosf(d * (PI_F / RCR_F)) + 0.5f;
                float u    = d - s_shfr[r];
                float term = 0.25f * expf(-etaR * u * u) * fc;
                atomicAdd(&rad[sp[j] * NSHFR + r], term);
            }
        }
    }

    // ---- angular AEV: warp-per-triple; 32 lanes = 4 ShfA x 8 ShfZ ----
    {
        const int   n    = nnbr;
        const int   wid  = tid >> 5;
        const int   lane = tid & 31;
        const int   sA   = lane >> 3;     // ShfA index
        const int   sZ   = lane & 7;      // ShfZ index
        const float cz   = s_cz[sZ];
        const float sz   = s_sz[sZ];
        const float sha  = s_shfa[sA];
        const float etaA = s_etaA;
        const float zeta = s_zeta;
        const bool  z32  = (zeta == 32.0f);

        for (int t = wid; t < n * n; t += NWARPS) {
            int jj = t / n;
            int kk = t - jj * n;
            if (jj >= kk) continue;       // unordered pair, term is j<->k symmetric
            int   j   = nbr[jj];
            int   k   = nbr[kk];
            float dij = dd[j];
            float dik = dd[k];
            float dot = vx[j] * vx[k] + vy[j] * vy[k] + vz[j] * vz[k];
            float c   = 0.95f * dot / (dij * dik);
            c = fminf(0.99f, fmaxf(-0.99f, c));
            float s    = sqrtf(1.0f - c * c);      // sin(arccos(c)) >= 0
            float davg = 0.5f * (dij + dik);
            float fcj  = 0.5f * cosf(dij * (PI_F / RCA_F)) + 0.5f;
            float fck  = 0.5f * cosf(dik * (PI_F / RCA_F)) + 0.5f;
            float fcp  = fcj * fck;
            int   p    = s_triu[sp[j] * NSPEC + sp[k]];

            // cos(theta - ShfZ) = c*cos(ShfZ) + sin(theta)*sin(ShfZ)
            float base = 0.5f * (1.0f + c * cz + s * sz);
            float f1;
            if (z32) {
                float b2 = base * base;
                float b4 = b2 * b2;
                float b8 = b4 * b4;
                float b16 = b8 * b8;
                f1 = b16 * b16;
            } else {
                f1 = __powf(base, zeta);
            }
            float u  = davg - sha;
            float f2 = expf(-etaA * u * u);
            atomicAdd(&ang[p * 32 + lane], 2.0f * f1 * f2 * fcp);
        }
    }
    __syncthreads();

    // ---- write out: 64 radial then 320 angular ----
    float* ob = out + mi * OUTDIM;
    #pragma unroll
    for (int t = tid; t < OUTDIM; t += NT)
        ob[t] = (t < RADDIM) ? rad[t] : ang[t - RADDIM];
}

extern "C" void kernel_launch(void* const* d_in, const int* in_sizes, int n_in,
                              void* d_out, int out_size)
{
    const float* coords  = (const float*)d_in[0];
    const float* etaR    = (const float*)d_in[1];
    const float* shfR    = (const float*)d_in[2];
    const float* etaA    = (const float*)d_in[3];
    const float* zeta    = (const float*)d_in[4];
    const float* shfA    = (const float*)d_in[5];
    const float* shfZ    = (const float*)d_in[6];
    const int*   spec    = (const int*)d_in[7];
    const int*   triu    = (const int*)d_in[8];
    float*       out     = (float*)d_out;

    aev_kernel<<<MM * AA, NT>>>(coords, etaR, shfR, etaA, zeta, shfA, shfZ,
                                spec, triu, out);
}

// round 2
// speedup vs baseline: 1.6154x; 1.6154x over previous
#include <cuda_runtime.h>
#include <math.h>

#define MM      8
#define AA      48
#define NSPEC   4
#define NPAIRCH 10
#define NSHFR   16
#define NSHFA   4
#define NSHFZ   8
#define RADDIM  (NSPEC * NSHFR)            /* 64  */
#define ANGDIM  (NPAIRCH * NSHFA * NSHFZ)  /* 320 */
#define OUTDIM  (RADDIM + ANGDIM)          /* 384 */
#define RCR_F   5.2f
#define RCA_F   3.5f
#define PI_F    3.14159265358979323846f
#define NT      256
#define NWARPS  (NT / 32)
#define MAXPAIR ((AA * (AA - 1)) / 2)      /* 1128 */

__global__ __launch_bounds__(NT, 1) void aev_kernel(
    const float* __restrict__ coords,   // (M, A, 3)
    const float* __restrict__ EtaR,     // (1,)
    const float* __restrict__ ShfR,     // (16,)
    const float* __restrict__ EtaA,     // (1,)
    const float* __restrict__ Zeta,     // (1,)
    const float* __restrict__ ShfA,     // (4,)
    const float* __restrict__ ShfZ,     // (8,)
    const int*   __restrict__ species,  // (M, A)
    const int*   __restrict__ triu,     // (4, 4)
    float*       __restrict__ out)      // (M, A, 384)
{
    __shared__ float px[AA], py[AA], pz[AA];
    __shared__ int   sp[AA];
    // radial per-j precompute: preR = 0.25*fc(d,RCR) if valid&in-range else 0
    __shared__ float dd[AA], preR[AA];
    // compacted neighbor arrays (d <= RCA)
    __shared__ float ux[AA], uy[AA], uz[AA], nd[AA], nfc[AA];
    __shared__ int   nsp[AA];
    __shared__ unsigned short pairs[MAXPAIR];
    __shared__ int   nnbr;
    __shared__ float rad[RADDIM];
    __shared__ float ang[ANGDIM];
    __shared__ float s_shfr[NSHFR], s_shfa[NSHFA];
    __shared__ float s_cz[NSHFZ], s_sz[NSHFZ];
    __shared__ int   s_triu[NSPEC * NSPEC];
    __shared__ float s_etaR, s_etaA, s_zeta;

    const int mi   = blockIdx.x;          // 0 .. M*A-1
    const int m    = mi / AA;
    const int i    = mi % AA;
    const int tid  = threadIdx.x;
    const int wid  = tid >> 5;
    const int lane = tid & 31;

    if (tid == 0) { nnbr = 0; s_etaR = EtaR[0]; s_etaA = EtaA[0]; s_zeta = Zeta[0]; }
    if (tid < NSHFR) s_shfr[tid] = ShfR[tid];
    if (tid < NSHFA) s_shfa[tid] = ShfA[tid];
    if (tid < NSHFZ) { float z = ShfZ[tid]; s_cz[tid] = __cosf(z); s_sz[tid] = __sinf(z); }
    if (tid < NSPEC * NSPEC) s_triu[tid] = triu[tid];
    if (tid < AA) {
        px[tid] = coords[(m * AA + tid) * 3 + 0];
        py[tid] = coords[(m * AA + tid) * 3 + 1];
        pz[tid] = coords[(m * AA + tid) * 3 + 2];
        sp[tid] = species[m * AA + tid];
    }
    if (tid < RADDIM) rad[tid] = 0.0f;
    #pragma unroll
    for (int t = tid; t < ANGDIM; t += NT) ang[t] = 0.0f;
    __syncthreads();

    const float xi  = px[i], yi = py[i], zi = pz[i];
    const int   spi = sp[i];

    // ---- distances, per-j radial precompute, compacted angular neighbor list ----
    if (tid < AA) {
        float dx = px[tid] - xi;          // v[m,i,j] = c[j] - c[i]
        float dy = py[tid] - yi;
        float dz = pz[tid] - zi;
        float d2 = dx * dx + dy * dy + dz * dz;
        float d  = sqrtf(d2 > 0.0f ? d2 : 1.0f);
        dd[tid] = d;
        bool pvb = (spi >= 0) && (sp[tid] >= 0) && (tid != i);
        // radial: precompute 0.25 * cutoff(d, RCR)
        float pr = 0.0f;
        if (pvb && d <= RCR_F)
            pr = 0.25f * (0.5f * __cosf(d * (PI_F / RCR_F)) + 0.5f);
        preR[tid] = pr;
        // angular neighbor: compact arrays with unit vector + cutoff
        if (pvb && d <= RCA_F) {
            int   idx = atomicAdd(&nnbr, 1);
            float rinv = 1.0f / d;
            ux[idx]  = dx * rinv;
            uy[idx]  = dy * rinv;
            uz[idx]  = dz * rinv;
            nd[idx]  = d;
            nfc[idx] = 0.5f * __cosf(d * (PI_F / RCA_F)) + 0.5f;
            nsp[idx] = sp[tid];
        }
    }
    __syncthreads();

    const int n = nnbr;

    // ---- build pair list (jj < kk), direct indexing, no atomics ----
    for (int jj = wid; jj < n; jj += NWARPS) {
        int rowbase = jj * (n - 1) - (jj * (jj - 1)) / 2 - jj - 1; // + kk
        for (int kk = jj + 1 + lane; kk < n; kk += 32)
            pairs[rowbase + kk] = (unsigned short)((jj << 8) | kk);
    }

    // ---- radial AEV: (j, r) work items, SMEM-atomic accumulation ----
    {
        const float etaR = s_etaR;
        #pragma unroll
        for (int t = tid; t < AA * NSHFR; t += NT) {
            int j = t >> 4;
            int r = t & 15;
            float pr = preR[j];
            if (pr != 0.0f) {
                float u = dd[j] - s_shfr[r];
                atomicAdd(&rad[sp[j] * NSHFR + r], pr * __expf(-etaR * u * u));
            }
        }
    }
    __syncthreads();

    // ---- angular AEV: warp-per-pair; 32 lanes = 4 ShfA x 8 ShfZ ----
    {
        const int   npairs = (n * (n - 1)) >> 1;
        const int   sA   = lane >> 3;     // ShfA index
        const int   sZ   = lane & 7;      // ShfZ index
        const float cz   = s_cz[sZ];
        const float sz   = s_sz[sZ];
        const float sha  = s_shfa[sA];
        const float etaA = s_etaA;
        const float zeta = s_zeta;
        const bool  z32  = (zeta == 32.0f);

        for (int t = wid; t < npairs; t += NWARPS) {
            int pk = pairs[t];
            int jj = pk >> 8;
            int kk = pk & 255;
            float c = 0.95f * (ux[jj] * ux[kk] + uy[jj] * uy[kk] + uz[jj] * uz[kk]);
            c = fminf(0.99f, fmaxf(-0.99f, c));
            float s    = sqrtf(1.0f - c * c);      // sin(arccos(c)) >= 0
            float davg = 0.5f * (nd[jj] + nd[kk]);
            float fcp2 = 2.0f * nfc[jj] * nfc[kk];
            int   p    = s_triu[nsp[jj] * NSPEC + nsp[kk]];

            // cos(theta - ShfZ) = c*cos(ShfZ) + sin(theta)*sin(ShfZ)
            float base = 0.5f + 0.5f * (c * cz + s * sz);
            float f1;
            if (z32) {
                float b2 = base * base;
                float b4 = b2 * b2;
                float b8 = b4 * b4;
                float b16 = b8 * b8;
                f1 = b16 * b16;
            } else {
                f1 = __powf(base, zeta);
            }
            float u  = davg - sha;
            float f2 = __expf(-etaA * u * u);
            atomicAdd(&ang[p * 32 + lane], f1 * f2 * fcp2);
        }
    }
    __syncthreads();

    // ---- write out: 64 radial then 320 angular ----
    float* ob = out + mi * OUTDIM;
    #pragma unroll
    for (int t = tid; t < OUTDIM; t += NT)
        ob[t] = (t < RADDIM) ? rad[t] : ang[t - RADDIM];
}

extern "C" void kernel_launch(void* const* d_in, const int* in_sizes, int n_in,
                              void* d_out, int out_size)
{
    const float* coordsp = (const float*)d_in[0];
    const float* etaR    = (const float*)d_in[1];
    const float* shfR    = (const float*)d_in[2];
    const float* etaA    = (const float*)d_in[3];
    const float* zeta    = (const float*)d_in[4];
    const float* shfA    = (const float*)d_in[5];
    const float* shfZ    = (const float*)d_in[6];
    const int*   spec    = (const int*)d_in[7];
    const int*   triu    = (const int*)d_in[8];
    float*       outp    = (float*)d_out;

    aev_kernel<<<MM * AA, NT>>>(coordsp, etaR, shfR, etaA, zeta, shfA, shfZ,
                                spec, triu, outp);
}

// round 3
// speedup vs baseline: 1.9592x; 1.2128x over previous
#include <cuda_runtime.h>
#include <math.h>

#define MM      8
#define AA      48
#define NSPEC   4
#define NPAIRCH 10
#define NSHFR   16
#define NSHFA   4
#define NSHFZ   8
#define RADDIM  (NSPEC * NSHFR)            /* 64  */
#define ANGDIM  (NPAIRCH * NSHFA * NSHFZ)  /* 320 */
#define OUTDIM  (RADDIM + ANGDIM)          /* 384 */
#define RCR_F   5.2f
#define RCA_F   3.5f
#define PI_F    3.14159265358979323846f
#define NT      512
#define NWARPS  (NT / 32)
#define MAXPAIR ((AA * (AA - 1)) / 2)      /* 1128 */

__global__ __launch_bounds__(NT, 1) void aev_kernel(
    const float* __restrict__ coords,   // (M, A, 3)
    const float* __restrict__ EtaR,     // (1,)
    const float* __restrict__ ShfR,     // (16,)
    const float* __restrict__ EtaA,     // (1,)
    const float* __restrict__ Zeta,     // (1,)
    const float* __restrict__ ShfA,     // (4,)
    const float* __restrict__ ShfZ,     // (8,)
    const int*   __restrict__ species,  // (M, A)
    const int*   __restrict__ triu,     // (4, 4)
    float*       __restrict__ out)      // (M, A, 384)
{
    __shared__ float px[AA], py[AA], pz[AA];
    __shared__ int   sp[AA];
    __shared__ float dd[AA], preR[AA];          // radial: d, 0.25*fc (0 if invalid)
    __shared__ float ux[AA], uy[AA], uz[AA];    // angular neighbors: unit vectors
    __shared__ float nd[AA], nfc[AA];
    __shared__ int   nsp[AA];
    __shared__ float4 pairdata[MAXPAIR];        // {cos, sin, davg, 2*fcj*fck}
    __shared__ unsigned char pairp[MAXPAIR];    // pair channel 0..9
    __shared__ int   nnbr;
    __shared__ float rad[RADDIM];
    __shared__ float ang[ANGDIM];
    __shared__ float s_shfr[NSHFR], s_shfa[NSHFA];
    __shared__ float s_cz[NSHFZ], s_sz[NSHFZ];
    __shared__ int   s_triu[NSPEC * NSPEC];
    __shared__ float s_etaR, s_etaA, s_zeta;

    const int mi   = blockIdx.x;          // 0 .. M*A-1
    const int m    = mi / AA;
    const int i    = mi % AA;
    const int tid  = threadIdx.x;
    const int wid  = tid >> 5;
    const int lane = tid & 31;

    if (tid == 0) { nnbr = 0; s_etaR = EtaR[0]; s_etaA = EtaA[0]; s_zeta = Zeta[0]; }
    if (tid < NSHFR) s_shfr[tid] = ShfR[tid];
    if (tid < NSHFA) s_shfa[tid] = ShfA[tid];
    if (tid < NSHFZ) { float z = ShfZ[tid]; s_cz[tid] = __cosf(z); s_sz[tid] = __sinf(z); }
    if (tid < NSPEC * NSPEC) s_triu[tid] = triu[tid];
    if (tid < AA) {
        px[tid] = coords[(m * AA + tid) * 3 + 0];
        py[tid] = coords[(m * AA + tid) * 3 + 1];
        pz[tid] = coords[(m * AA + tid) * 3 + 2];
        sp[tid] = species[m * AA + tid];
    }
    if (tid < RADDIM) rad[tid] = 0.0f;
    if (tid < ANGDIM) ang[tid] = 0.0f;
    __syncthreads();

    const float xi  = px[i], yi = py[i], zi = pz[i];
    const int   spi = sp[i];

    // ---- distances, radial precompute, compacted angular neighbor list ----
    if (tid < AA) {
        float dx = px[tid] - xi;          // v[m,i,j] = c[j] - c[i]
        float dy = py[tid] - yi;
        float dz = pz[tid] - zi;
        float d2 = dx * dx + dy * dy + dz * dz;
        float d  = sqrtf(d2 > 0.0f ? d2 : 1.0f);
        dd[tid] = d;
        bool pvb = (spi >= 0) && (sp[tid] >= 0) && (tid != i);
        float pr = 0.0f;
        if (pvb && d <= RCR_F)
            pr = 0.25f * (0.5f * __cosf(d * (PI_F / RCR_F)) + 0.5f);
        preR[tid] = pr;
        if (pvb && d <= RCA_F) {
            int   idx  = atomicAdd(&nnbr, 1);
            float rinv = 1.0f / d;
            ux[idx]  = dx * rinv;
            uy[idx]  = dy * rinv;
            uz[idx]  = dz * rinv;
            nd[idx]  = d;
            nfc[idx] = 0.5f * __cosf(d * (PI_F / RCA_F)) + 0.5f;
            nsp[idx] = sp[tid];
        }
    }
    __syncthreads();

    const int n = nnbr;

    // ---- pair-scalar precompute: one thread per (jj<kk) pair ----
    for (int t = tid; t < n * n; t += NT) {
        int jj = t / n;
        int kk = t - jj * n;
        if (jj < kk) {
            int idx = jj * (n - 1) - (jj * (jj - 1)) / 2 - jj - 1 + kk;
            float c = 0.95f * (ux[jj] * ux[kk] + uy[jj] * uy[kk] + uz[jj] * uz[kk]);
            c = fminf(0.99f, fmaxf(-0.99f, c));
            float s = sqrtf(1.0f - c * c);         // sin(arccos(c)) >= 0
            float4 pd;
            pd.x = c;
            pd.y = s;
            pd.z = 0.5f * (nd[jj] + nd[kk]);       // davg
            pd.w = 2.0f * nfc[jj] * nfc[kk];       // 2*fcj*fck
            pairdata[idx] = pd;
            pairp[idx] = (unsigned char)s_triu[nsp[jj] * NSPEC + nsp[kk]];
        }
    }

    // ---- radial AEV: (j, r) work items, SMEM-atomic accumulation ----
    {
        const float etaR = s_etaR;
        #pragma unroll
        for (int t = tid; t < AA * NSHFR; t += NT) {
            int j = t >> 4;
            int r = t & 15;
            float pr = preR[j];
            if (pr != 0.0f) {
                float u = dd[j] - s_shfr[r];
                atomicAdd(&rad[sp[j] * NSHFR + r], pr * __expf(-etaR * u * u));
            }
        }
    }
    __syncthreads();

    // ---- angular AEV: warp-per-pair; 32 lanes = 4 ShfA x 8 ShfZ ----
    {
        const int   npairs = (n * (n - 1)) >> 1;
        const int   sA   = lane >> 3;     // ShfA index
        const int   sZ   = lane & 7;      // ShfZ index
        const float cz   = s_cz[sZ];
        const float sz   = s_sz[sZ];
        const float sha  = s_shfa[sA];
        const float etaA = s_etaA;
        const float zeta = s_zeta;
        const bool  z32  = (zeta == 32.0f);

        #pragma unroll 2
        for (int t = wid; t < npairs; t += NWARPS) {
            float4 pd = pairdata[t];                   // broadcast LDS.128
            int    p  = pairp[t];
            // cos(theta - ShfZ) = c*cos(ShfZ) + sin(theta)*sin(ShfZ)
            float base = 0.5f + 0.5f * (pd.x * cz + pd.y * sz);
            float f1;
            if (z32) {
                float b2 = base * base;
                float b4 = b2 * b2;
                float b8 = b4 * b4;
                float b16 = b8 * b8;
                f1 = b16 * b16;
            } else {
                f1 = __powf(base, zeta);
            }
            float u  = pd.z - sha;
            float f2 = __expf(-etaA * u * u);
            atomicAdd(&ang[p * 32 + lane], f1 * f2 * pd.w);
        }
    }
    __syncthreads();

    // ---- write out: 64 radial then 320 angular (single pass, 512 >= 384) ----
    if (tid < OUTDIM) {
        float* ob = out + mi * OUTDIM;
        ob[tid] = (tid < RADDIM) ? rad[tid] : ang[tid - RADDIM];
    }
}

extern "C" void kernel_launch(void* const* d_in, const int* in_sizes, int n_in,
                              void* d_out, int out_size)
{
    const float* coordsp = (const float*)d_in[0];
    const float* etaR    = (const float*)d_in[1];
    const float* shfR    = (const float*)d_in[2];
    const float* etaA    = (const float*)d_in[3];
    const float* zeta    = (const float*)d_in[4];
    const float* shfA    = (const float*)d_in[5];
    const float* shfZ    = (const float*)d_in[6];
    const int*   spec    = (const int*)d_in[7];
    const int*   triu    = (const int*)d_in[8];
    float*       outp    = (float*)d_out;

    aev_kernel<<<MM * AA, NT>>>(coordsp, etaR, shfR, etaA, zeta, shfA, shfZ,
                                spec, triu, outp);
}